// round 6
// baseline (speedup 1.0000x reference)
#include <cuda_runtime.h>
#include <math.h>

#define BATCH 32
#define NPTS 4096
#define IDIM 125
#define ADIM 128
#define KDIM 64
#define DMODEL 1024
#define HID 64
#define KSEL 256
#define EPSV 1e-6f

// ---------------- scratch (device globals; no allocation allowed) ----------------
__device__ float g_sal[BATCH * NPTS];
__device__ float g_csal[BATCH * NPTS];
__device__ int   g_topidx[BATCH * KSEL];
__device__ float g_cloud[BATCH * KSEL * KDIM];   // [8192][64]

// ---------------- kernel 1: fused saliency MLP (register-blocked) ----------------
// tile: 128 points x 64 hidden, 2 tiles per block (W1 stays resident).
// 256 threads; micro-tile 4 points x 8 hidden.
#define SAL_TILE_PTS 128
#define SAL_TILES 2
#define SX_STRIDE 129
__global__ __launch_bounds__(256) void saliency_kernel(
    const float* __restrict__ x, const float* __restrict__ W1,
    const float* __restrict__ b1, const float* __restrict__ W2,
    const float* __restrict__ b2)
{
    extern __shared__ float dynsm[];
    float* W1s = dynsm;                 // [125][64]
    float* sx  = dynsm + IDIM * HID;    // [128][129]

    const int ptsPerBlock = SAL_TILE_PTS * SAL_TILES;       // 256
    const int groupsPerBatch = NPTS / ptsPerBlock;          // 16
    const int b  = blockIdx.x / groupsPerBatch;
    const int gp = blockIdx.x % groupsPerBatch;
    const int tid = threadIdx.x;

    for (int i = tid; i < IDIM * HID; i += 256) W1s[i] = W1[i];

    const int hg = tid & 7;        // 8 hidden groups of 8
    const int pg = tid >> 3;       // 32 point groups of 4
    const int h0 = hg * 8;

    float4 b1a = *(const float4*)(b1 + h0);
    float4 b1b = *(const float4*)(b1 + h0 + 4);
    float4 w2a = *(const float4*)(W2 + h0);
    float4 w2b = *(const float4*)(W2 + h0 + 4);
    const float bias = b2[0];

    for (int t = 0; t < SAL_TILES; t++) {
        const int p0 = (gp * SAL_TILES + t) * SAL_TILE_PTS;
        const float* xbase = x + ((long)b * NPTS + p0) * IDIM;
        __syncthreads();
        for (int i = tid; i < SAL_TILE_PTS * IDIM; i += 256) {
            int p = i / IDIM, d = i - p * IDIM;
            sx[p * SX_STRIDE + d] = xbase[i];
        }
        __syncthreads();

        float a0[8], a1[8], a2[8], a3[8];
        a0[0]=b1a.x; a0[1]=b1a.y; a0[2]=b1a.z; a0[3]=b1a.w; a0[4]=b1b.x; a0[5]=b1b.y; a0[6]=b1b.z; a0[7]=b1b.w;
#pragma unroll
        for (int j = 0; j < 8; j++) { a1[j]=a0[j]; a2[j]=a0[j]; a3[j]=a0[j]; }

        const float* r0 = sx + (pg * 4 + 0) * SX_STRIDE;
        const float* r1 = sx + (pg * 4 + 1) * SX_STRIDE;
        const float* r2 = sx + (pg * 4 + 2) * SX_STRIDE;
        const float* r3 = sx + (pg * 4 + 3) * SX_STRIDE;
#pragma unroll 5
        for (int d = 0; d < IDIM; d++) {
            float x0 = r0[d], x1 = r1[d], x2 = r2[d], x3 = r3[d];
            float4 wa = *(const float4*)(W1s + d * HID + h0);
            float4 wb = *(const float4*)(W1s + d * HID + h0 + 4);
            float w[8] = {wa.x, wa.y, wa.z, wa.w, wb.x, wb.y, wb.z, wb.w};
#pragma unroll
            for (int j = 0; j < 8; j++) {
                a0[j] = fmaf(x0, w[j], a0[j]);
                a1[j] = fmaf(x1, w[j], a1[j]);
                a2[j] = fmaf(x2, w[j], a2[j]);
                a3[j] = fmaf(x3, w[j], a3[j]);
            }
        }
        float w2[8] = {w2a.x, w2a.y, w2a.z, w2a.w, w2b.x, w2b.y, w2b.z, w2b.w};
        float s0 = 0.f, s1 = 0.f, s2 = 0.f, s3 = 0.f;
#pragma unroll
        for (int j = 0; j < 8; j++) {
            s0 = fmaf(fmaxf(a0[j], 0.f), w2[j], s0);
            s1 = fmaf(fmaxf(a1[j], 0.f), w2[j], s1);
            s2 = fmaf(fmaxf(a2[j], 0.f), w2[j], s2);
            s3 = fmaf(fmaxf(a3[j], 0.f), w2[j], s3);
        }
#pragma unroll
        for (int off = 4; off > 0; off >>= 1) {
            s0 += __shfl_down_sync(0xFFFFFFFFu, s0, off, 8);
            s1 += __shfl_down_sync(0xFFFFFFFFu, s1, off, 8);
            s2 += __shfl_down_sync(0xFFFFFFFFu, s2, off, 8);
            s3 += __shfl_down_sync(0xFFFFFFFFu, s3, off, 8);
        }
        if (hg == 0) {
            float* o = g_sal + b * NPTS + p0 + pg * 4;
            float4 r;
            r.x = 1.f / (1.f + expf(-(s0 + bias)));
            r.y = 1.f / (1.f + expf(-(s1 + bias)));
            r.z = 1.f / (1.f + expf(-(s2 + bias)));
            r.w = 1.f / (1.f + expf(-(s3 + bias)));
            *(float4*)o = r;
        }
    }
}

// ---------------- kernel 2: per-batch softmax + cumsum ----------------
__global__ __launch_bounds__(1024) void scan_kernel(float* __restrict__ ystar)
{
    __shared__ float wsum[32];
    __shared__ float woff[32];
    __shared__ float wesum[32];
    __shared__ float total_sh;

    const int b = blockIdx.x;
    const int tid = threadIdx.x;
    const int lane = tid & 31, wid = tid >> 5;

    float4 s4 = *(const float4*)(g_sal + b * NPTS + tid * 4);
    float s0 = s4.x;
    float s1 = s0 + s4.y;
    float s2 = s1 + s4.z;
    float s3 = s2 + s4.w;

    float e0 = expf(2.f * s4.x), e1 = expf(2.f * s4.y);
    float e2 = expf(2.f * s4.z), e3 = expf(2.f * s4.w);
    float esum = e0 + e1 + e2 + e3;

    float t = s3, incl = t;
#pragma unroll
    for (int off = 1; off < 32; off <<= 1) {
        float v = __shfl_up_sync(0xFFFFFFFFu, incl, off);
        if (lane >= off) incl += v;
    }
    float er = esum;
#pragma unroll
    for (int off = 16; off > 0; off >>= 1) er += __shfl_down_sync(0xFFFFFFFFu, er, off);
    if (lane == 31) wsum[wid] = incl;
    if (lane == 0)  wesum[wid] = er;
    __syncthreads();
    if (wid == 0) {
        float v = wsum[lane];
        float inc = v;
#pragma unroll
        for (int off = 1; off < 32; off <<= 1) {
            float u = __shfl_up_sync(0xFFFFFFFFu, inc, off);
            if (lane >= off) inc += u;
        }
        woff[lane] = inc - v;
        float es = wesum[lane];
#pragma unroll
        for (int off = 16; off > 0; off >>= 1) es += __shfl_down_sync(0xFFFFFFFFu, es, off);
        if (lane == 0) total_sh = es;
    }
    __syncthreads();

    float base = woff[wid] + (incl - t);
    const float invn = 1.f / (float)NPTS;
    float4 c4;
    c4.x = (base + s0) * invn;
    c4.y = (base + s1) * invn;
    c4.z = (base + s2) * invn;
    c4.w = (base + s3) * invn;
    *(float4*)(g_csal + b * NPTS + tid * 4) = c4;

    float invtot = 1.f / total_sh;
    float4 y4;
    y4.x = e0 * invtot; y4.y = e1 * invtot; y4.z = e2 * invtot; y4.w = e3 * invtot;
    *(float4*)(ystar + b * NPTS + tid * 4) = y4;
}

// ---------------- kernel 3: per-batch top-256 via bitonic sort ----------------
__global__ __launch_bounds__(1024) void topk_kernel(const float* __restrict__ ystar)
{
    __shared__ unsigned long long keys[NPTS];
    const int b = blockIdx.x;
    const int tid = threadIdx.x;

    for (int i = tid; i < NPTS; i += 1024) {
        unsigned u = __float_as_uint(ystar[b * NPTS + i]);
        unsigned m = (u & 0x80000000u) ? ~u : (u | 0x80000000u);
        unsigned inv = ~m;
        keys[i] = ((unsigned long long)inv << 32) | (unsigned)i;
    }
    __syncthreads();

    for (int k = 2; k <= NPTS; k <<= 1) {
        for (int j = k >> 1; j > 0; j >>= 1) {
#pragma unroll 4
            for (int i = tid; i < NPTS; i += 1024) {
                int ixj = i ^ j;
                if (ixj > i) {
                    bool up = ((i & k) == 0);
                    unsigned long long a = keys[i];
                    unsigned long long c = keys[ixj];
                    if ((a > c) == up) { keys[i] = c; keys[ixj] = a; }
                }
            }
            __syncthreads();
        }
    }
    for (int t2 = tid; t2 < KSEL; t2 += 1024)
        g_topidx[b * KSEL + t2] = (int)(keys[t2] & 0xFFFFFFFFu);
}

// ---------------- kernel 4: anchor + normalize + lift (reg-light) ----------------
// one block per 16 selected points; 256 threads. Writes g_cloud.
#define AS_STRIDE 132
__global__ __launch_bounds__(256) void lift_kernel(
    const float* __restrict__ x, const float* __restrict__ lift_W,
    const float* __restrict__ lift_b, const float* __restrict__ mu,
    const float* __restrict__ sigma)
{
    __shared__ float Ws[ADIM * KDIM];      // 32KB
    __shared__ float a_s[16][AS_STRIDE];   // 8.25KB

    const int tid = threadIdx.x;
    const int p0 = blockIdx.x * 16;        // selected-point base (0..8191)

    for (int i = tid; i < ADIM * KDIM; i += 256) Ws[i] = lift_W[i];

    // ---- stage 1: gather + L2-normalize + standardize ----
    {
        const int grp = tid >> 4;          // point 0..15
        const int sub = tid & 15;          // dim chunk: 8 dims each
        const int gk = p0 + grp;
        const int b = gk / KSEL;
        const int idx = g_topidx[gk];
        const float* xr = x + ((long)b * NPTS + idx) * IDIM;
        float sal = g_sal[b * NPTS + idx];
        float csv = g_csal[b * NPTS + idx];
        float pos = (float)idx * (1.f / (float)(NPTS - 1));

        float v[8];
#pragma unroll
        for (int q = 0; q < 8; q++) {
            int d = sub * 8 + q;
            float val;
            if (d < IDIM)       val = xr[d];
            else if (d == 125)  val = sal;
            else if (d == 126)  val = pos;
            else                val = csv;
            v[q] = val;
        }
        float ss = 0.f;
#pragma unroll
        for (int q = 0; q < 8; q++) ss = fmaf(v[q], v[q], ss);
#pragma unroll
        for (int off = 8; off > 0; off >>= 1)
            ss += __shfl_xor_sync(0xFFFFFFFFu, ss, off, 16);
        float inv_nrm = 1.f / (sqrtf(ss) + EPSV);
#pragma unroll
        for (int q = 0; q < 8; q++) {
            int d = sub * 8 + q;
            a_s[grp][d] = (v[q] * inv_nrm - mu[d]) / sigma[d];
        }
    }
    __syncthreads();

    // ---- stage 2: cloud = a_s @ lift_W + lift_b ----
    {
        const int pt = tid >> 4;
        const int c4 = (tid & 15) * 4;
        float4 acc = *(const float4*)(lift_b + c4);
#pragma unroll 8
        for (int d = 0; d < ADIM; d++) {
            float s = a_s[pt][d];
            float4 w = *(const float4*)(Ws + d * KDIM + c4);
            acc.x = fmaf(s, w.x, acc.x);
            acc.y = fmaf(s, w.y, acc.y);
            acc.z = fmaf(s, w.z, acc.z);
            acc.w = fmaf(s, w.w, acc.w);
        }
        *(float4*)(g_cloud + (p0 + pt) * KDIM + c4) = acc;
    }
}

// ---------------- kernel 5: projection GEMM [8192,64]@[64,1024]+b ----------------
// block: 64 points x 128 cols; 256 threads; thread: 8 pts x 4 cols (32 acc regs).
// grid: (8192/64, 1024/128) = (128, 8).
__global__ __launch_bounds__(256) void proj_kernel(
    const float* __restrict__ proj_W, const float* __restrict__ proj_b,
    float* __restrict__ tokens)
{
    __shared__ float cs[64 * KDIM]; // 16KB
    const int tid = threadIdx.x;
    const int p0 = blockIdx.x * 64;
    const int col0 = blockIdx.y * 128;

    for (int i = tid; i < 64 * KDIM; i += 256)
        cs[i] = g_cloud[p0 * KDIM + i];
    __syncthreads();

    const int cg = (tid & 31) * 4;     // col within 128-col block
    const int pg = (tid >> 5) * 8;     // point group of 8

    float4 acc[8];
#pragma unroll
    for (int p = 0; p < 8; p++) acc[p] = make_float4(0.f, 0.f, 0.f, 0.f);

#pragma unroll 4
    for (int c = 0; c < KDIM; c++) {
        float4 w4 = *(const float4*)(proj_W + c * DMODEL + col0 + cg);
#pragma unroll
        for (int p = 0; p < 8; p++) {
            float s = cs[(pg + p) * KDIM + c];
            acc[p].x = fmaf(s, w4.x, acc[p].x);
            acc[p].y = fmaf(s, w4.y, acc[p].y);
            acc[p].z = fmaf(s, w4.z, acc[p].z);
            acc[p].w = fmaf(s, w4.w, acc[p].w);
        }
    }
    float4 pb = *(const float4*)(proj_b + col0 + cg);
#pragma unroll
    for (int p = 0; p < 8; p++) {
        float4 o;
        o.x = acc[p].x + pb.x; o.y = acc[p].y + pb.y;
        o.z = acc[p].z + pb.z; o.w = acc[p].w + pb.w;
        *(float4*)(tokens + (long)(p0 + pg + p) * DMODEL + col0 + cg) = o;
    }
}

// ---------------- launcher ----------------
extern "C" void kernel_launch(void* const* d_in, const int* in_sizes, int n_in,
                              void* d_out, int out_size)
{
    const float* x      = (const float*)d_in[0];
    const float* W1     = (const float*)d_in[1];
    const float* b1     = (const float*)d_in[2];
    const float* W2     = (const float*)d_in[3];
    const float* b2     = (const float*)d_in[4];
    const float* lift_W = (const float*)d_in[5];
    const float* lift_b = (const float*)d_in[6];
    const float* mu     = (const float*)d_in[7];
    const float* sigma  = (const float*)d_in[8];
    const float* proj_W = (const float*)d_in[9];
    const float* proj_b = (const float*)d_in[10];

    float* tokens = (float*)d_out;                        // [B,256,1024]
    float* ystar  = tokens + (long)BATCH * KSEL * DMODEL; // [B,4096]

    const int salSmem = (IDIM * HID + SAL_TILE_PTS * SX_STRIDE) * sizeof(float); // 98048 B
    cudaFuncSetAttribute(saliency_kernel, cudaFuncAttributeMaxDynamicSharedMemorySize, salSmem);

    saliency_kernel<<<BATCH * (NPTS / (SAL_TILE_PTS * SAL_TILES)), 256, salSmem>>>(x, W1, b1, W2, b2);
    scan_kernel<<<BATCH, 1024>>>(ystar);
    topk_kernel<<<BATCH, 1024>>>(ystar);
    lift_kernel<<<BATCH * KSEL / 16, 256>>>(x, lift_W, lift_b, mu, sigma);
    dim3 pgrid(BATCH * KSEL / 64, DMODEL / 128);
    proj_kernel<<<pgrid, 256>>>(proj_W, proj_b, tokens);
}

// round 7
// speedup vs baseline: 1.1396x; 1.1396x over previous
#include <cuda_runtime.h>
#include <math.h>

#define BATCH 32
#define NPTS 4096
#define IDIM 125
#define ADIM 128
#define KDIM 64
#define DMODEL 1024
#define HID 64
#define KSEL 256
#define EPSV 1e-6f

typedef unsigned long long ull;

// ---------------- f32x2 packed-FMA helpers (sm_103a) ----------------
__device__ __forceinline__ ull pack2(float lo, float hi) {
    ull r; asm("mov.b64 %0, {%1, %2};" : "=l"(r) : "f"(lo), "f"(hi)); return r;
}
__device__ __forceinline__ ull dup2(float v) { return pack2(v, v); }
__device__ __forceinline__ float2 unpack2(ull v) {
    float2 f; asm("mov.b64 {%0, %1}, %2;" : "=f"(f.x), "=f"(f.y) : "l"(v)); return f;
}
__device__ __forceinline__ ull ffma2(ull a, ull b, ull c) {
    ull d; asm("fma.rn.f32x2 %0, %1, %2, %3;" : "=l"(d) : "l"(a), "l"(b), "l"(c)); return d;
}

// ---------------- scratch (device globals; no allocation allowed) ----------------
__device__ float g_sal[BATCH * NPTS];
__device__ float g_csal[BATCH * NPTS];
__device__ int   g_topidx[BATCH * KSEL];
__device__ float g_cloud[BATCH * KSEL * KDIM];   // [8192][64]

// ---------------- kernel 1: fused saliency MLP (f32x2 packed) ----------------
// tile: 128 points x 64 hidden, 2 tiles per block (W1 resident in smem).
// 256 threads; micro-tile 4 points x 8 hidden = 16 FFMA2 per d per thread.
#define SAL_TILE_PTS 128
#define SAL_TILES 2
#define SX_STRIDE 129
__global__ __launch_bounds__(256) void saliency_kernel(
    const float* __restrict__ x, const float* __restrict__ W1,
    const float* __restrict__ b1, const float* __restrict__ W2,
    const float* __restrict__ b2)
{
    extern __shared__ float dynsm[];
    float* W1s = dynsm;                 // [125][64]
    float* sx  = dynsm + IDIM * HID;    // [128][129]

    const int ptsPerBlock = SAL_TILE_PTS * SAL_TILES;       // 256
    const int groupsPerBatch = NPTS / ptsPerBlock;          // 16
    const int b  = blockIdx.x / groupsPerBatch;
    const int gp = blockIdx.x % groupsPerBatch;
    const int tid = threadIdx.x;

    for (int i = tid; i < IDIM * HID; i += 256) W1s[i] = W1[i];

    const int hg = tid & 7;        // 8 hidden groups of 8
    const int pg = tid >> 3;       // 32 point groups of 4
    const int h0 = hg * 8;

    // b1 / W2 pairs for this hidden group (8-byte aligned: h0 multiple of 8)
    const ull* b1p = (const ull*)(b1 + h0);
    ull bini[4] = {b1p[0], b1p[1], b1p[2], b1p[3]};
    float4 w2a = *(const float4*)(W2 + h0);
    float4 w2b = *(const float4*)(W2 + h0 + 4);
    const float w2s[8] = {w2a.x, w2a.y, w2a.z, w2a.w, w2b.x, w2b.y, w2b.z, w2b.w};
    const float bias = b2[0];

    for (int t = 0; t < SAL_TILES; t++) {
        const int p0 = (gp * SAL_TILES + t) * SAL_TILE_PTS;
        const float* xbase = x + ((long)b * NPTS + p0) * IDIM;
        __syncthreads();
        for (int i = tid; i < SAL_TILE_PTS * IDIM; i += 256) {
            int p = i / IDIM, d = i - p * IDIM;
            sx[p * SX_STRIDE + d] = xbase[i];
        }
        __syncthreads();

        // packed accumulators: A[q][j] = hidden pair (h0+2j, h0+2j+1) for point q
        ull A0[4], A1[4], A2[4], A3[4];
#pragma unroll
        for (int j = 0; j < 4; j++) { A0[j]=bini[j]; A1[j]=bini[j]; A2[j]=bini[j]; A3[j]=bini[j]; }

        const float* r0 = sx + (pg * 4 + 0) * SX_STRIDE;
        const float* r1 = sx + (pg * 4 + 1) * SX_STRIDE;
        const float* r2 = sx + (pg * 4 + 2) * SX_STRIDE;
        const float* r3 = sx + (pg * 4 + 3) * SX_STRIDE;
#pragma unroll 5
        for (int d = 0; d < IDIM; d++) {
            ull X0 = dup2(r0[d]);
            ull X1 = dup2(r1[d]);
            ull X2 = dup2(r2[d]);
            ull X3 = dup2(r3[d]);
            const ull* wrow = (const ull*)(W1s + d * HID + h0); // 8B aligned
            ull w0 = wrow[0], w1 = wrow[1], w2 = wrow[2], w3 = wrow[3];
            A0[0]=ffma2(X0,w0,A0[0]); A0[1]=ffma2(X0,w1,A0[1]); A0[2]=ffma2(X0,w2,A0[2]); A0[3]=ffma2(X0,w3,A0[3]);
            A1[0]=ffma2(X1,w0,A1[0]); A1[1]=ffma2(X1,w1,A1[1]); A1[2]=ffma2(X1,w2,A1[2]); A1[3]=ffma2(X1,w3,A1[3]);
            A2[0]=ffma2(X2,w0,A2[0]); A2[1]=ffma2(X2,w1,A2[1]); A2[2]=ffma2(X2,w2,A2[2]); A2[3]=ffma2(X2,w3,A2[3]);
            A3[0]=ffma2(X3,w0,A3[0]); A3[1]=ffma2(X3,w1,A3[1]); A3[2]=ffma2(X3,w2,A3[2]); A3[3]=ffma2(X3,w3,A3[3]);
        }
        // relu + dot with W2 slice
        float s0 = 0.f, s1 = 0.f, s2 = 0.f, s3 = 0.f;
#pragma unroll
        for (int j = 0; j < 4; j++) {
            float2 u0 = unpack2(A0[j]), u1 = unpack2(A1[j]);
            float2 u2 = unpack2(A2[j]), u3 = unpack2(A3[j]);
            s0 = fmaf(fmaxf(u0.x,0.f), w2s[2*j], fmaf(fmaxf(u0.y,0.f), w2s[2*j+1], s0));
            s1 = fmaf(fmaxf(u1.x,0.f), w2s[2*j], fmaf(fmaxf(u1.y,0.f), w2s[2*j+1], s1));
            s2 = fmaf(fmaxf(u2.x,0.f), w2s[2*j], fmaf(fmaxf(u2.y,0.f), w2s[2*j+1], s2));
            s3 = fmaf(fmaxf(u3.x,0.f), w2s[2*j], fmaf(fmaxf(u3.y,0.f), w2s[2*j+1], s3));
        }
        // reduce across the 8 hg lanes (consecutive lanes, width 8)
#pragma unroll
        for (int off = 4; off > 0; off >>= 1) {
            s0 += __shfl_down_sync(0xFFFFFFFFu, s0, off, 8);
            s1 += __shfl_down_sync(0xFFFFFFFFu, s1, off, 8);
            s2 += __shfl_down_sync(0xFFFFFFFFu, s2, off, 8);
            s3 += __shfl_down_sync(0xFFFFFFFFu, s3, off, 8);
        }
        if (hg == 0) {
            float* o = g_sal + b * NPTS + p0 + pg * 4;
            float4 r;
            r.x = 1.f / (1.f + expf(-(s0 + bias)));
            r.y = 1.f / (1.f + expf(-(s1 + bias)));
            r.z = 1.f / (1.f + expf(-(s2 + bias)));
            r.w = 1.f / (1.f + expf(-(s3 + bias)));
            *(float4*)o = r;
        }
    }
}

// ---------------- kernel 2: per-batch softmax + cumsum ----------------
__global__ __launch_bounds__(1024) void scan_kernel(float* __restrict__ ystar)
{
    __shared__ float wsum[32];
    __shared__ float woff[32];
    __shared__ float wesum[32];
    __shared__ float total_sh;

    const int b = blockIdx.x;
    const int tid = threadIdx.x;
    const int lane = tid & 31, wid = tid >> 5;

    float4 s4 = *(const float4*)(g_sal + b * NPTS + tid * 4);
    float s0 = s4.x;
    float s1 = s0 + s4.y;
    float s2 = s1 + s4.z;
    float s3 = s2 + s4.w;

    float e0 = expf(2.f * s4.x), e1 = expf(2.f * s4.y);
    float e2 = expf(2.f * s4.z), e3 = expf(2.f * s4.w);
    float esum = e0 + e1 + e2 + e3;

    float t = s3, incl = t;
#pragma unroll
    for (int off = 1; off < 32; off <<= 1) {
        float v = __shfl_up_sync(0xFFFFFFFFu, incl, off);
        if (lane >= off) incl += v;
    }
    float er = esum;
#pragma unroll
    for (int off = 16; off > 0; off >>= 1) er += __shfl_down_sync(0xFFFFFFFFu, er, off);
    if (lane == 31) wsum[wid] = incl;
    if (lane == 0)  wesum[wid] = er;
    __syncthreads();
    if (wid == 0) {
        float v = wsum[lane];
        float inc = v;
#pragma unroll
        for (int off = 1; off < 32; off <<= 1) {
            float u = __shfl_up_sync(0xFFFFFFFFu, inc, off);
            if (lane >= off) inc += u;
        }
        woff[lane] = inc - v;
        float es = wesum[lane];
#pragma unroll
        for (int off = 16; off > 0; off >>= 1) es += __shfl_down_sync(0xFFFFFFFFu, es, off);
        if (lane == 0) total_sh = es;
    }
    __syncthreads();

    float base = woff[wid] + (incl - t);
    const float invn = 1.f / (float)NPTS;
    float4 c4;
    c4.x = (base + s0) * invn;
    c4.y = (base + s1) * invn;
    c4.z = (base + s2) * invn;
    c4.w = (base + s3) * invn;
    *(float4*)(g_csal + b * NPTS + tid * 4) = c4;

    float invtot = 1.f / total_sh;
    float4 y4;
    y4.x = e0 * invtot; y4.y = e1 * invtot; y4.z = e2 * invtot; y4.w = e3 * invtot;
    *(float4*)(ystar + b * NPTS + tid * 4) = y4;
}

// ---------------- kernel 3: per-batch top-256 via bitonic sort ----------------
__global__ __launch_bounds__(1024) void topk_kernel(const float* __restrict__ ystar)
{
    __shared__ unsigned long long keys[NPTS];
    const int b = blockIdx.x;
    const int tid = threadIdx.x;

    for (int i = tid; i < NPTS; i += 1024) {
        unsigned u = __float_as_uint(ystar[b * NPTS + i]);
        unsigned m = (u & 0x80000000u) ? ~u : (u | 0x80000000u);
        unsigned inv = ~m;
        keys[i] = ((unsigned long long)inv << 32) | (unsigned)i;
    }
    __syncthreads();

    for (int k = 2; k <= NPTS; k <<= 1) {
        for (int j = k >> 1; j > 0; j >>= 1) {
#pragma unroll 4
            for (int i = tid; i < NPTS; i += 1024) {
                int ixj = i ^ j;
                if (ixj > i) {
                    bool up = ((i & k) == 0);
                    unsigned long long a = keys[i];
                    unsigned long long c = keys[ixj];
                    if ((a > c) == up) { keys[i] = c; keys[ixj] = a; }
                }
            }
            __syncthreads();
        }
    }
    for (int t2 = tid; t2 < KSEL; t2 += 1024)
        g_topidx[b * KSEL + t2] = (int)(keys[t2] & 0xFFFFFFFFu);
}

// ---------------- kernel 4: anchor + normalize + lift ----------------
#define AS_STRIDE 132
__global__ __launch_bounds__(256) void lift_kernel(
    const float* __restrict__ x, const float* __restrict__ lift_W,
    const float* __restrict__ lift_b, const float* __restrict__ mu,
    const float* __restrict__ sigma)
{
    __shared__ float Ws[ADIM * KDIM];      // 32KB
    __shared__ float a_s[16][AS_STRIDE];   // 8.25KB

    const int tid = threadIdx.x;
    const int p0 = blockIdx.x * 16;        // selected-point base (0..8191)

    for (int i = tid; i < ADIM * KDIM; i += 256) Ws[i] = lift_W[i];

    // ---- stage 1: gather + L2-normalize + standardize ----
    {
        const int grp = tid >> 4;          // point 0..15
        const int sub = tid & 15;          // dim chunk: 8 dims each
        const int gk = p0 + grp;
        const int b = gk / KSEL;
        const int idx = g_topidx[gk];
        const float* xr = x + ((long)b * NPTS + idx) * IDIM;
        float sal = g_sal[b * NPTS + idx];
        float csv = g_csal[b * NPTS + idx];
        float pos = (float)idx * (1.f / (float)(NPTS - 1));

        float v[8];
#pragma unroll
        for (int q = 0; q < 8; q++) {
            int d = sub * 8 + q;
            float val;
            if (d < IDIM)       val = xr[d];
            else if (d == 125)  val = sal;
            else if (d == 126)  val = pos;
            else                val = csv;
            v[q] = val;
        }
        float ss = 0.f;
#pragma unroll
        for (int q = 0; q < 8; q++) ss = fmaf(v[q], v[q], ss);
#pragma unroll
        for (int off = 8; off > 0; off >>= 1)
            ss += __shfl_xor_sync(0xFFFFFFFFu, ss, off, 16);
        float inv_nrm = 1.f / (sqrtf(ss) + EPSV);
#pragma unroll
        for (int q = 0; q < 8; q++) {
            int d = sub * 8 + q;
            a_s[grp][d] = (v[q] * inv_nrm - mu[d]) / sigma[d];
        }
    }
    __syncthreads();

    // ---- stage 2: cloud = a_s @ lift_W + lift_b (f32x2 packed) ----
    {
        const int pt = tid >> 4;
        const int c4 = (tid & 15) * 4;
        const ull* lbp = (const ull*)(lift_b + c4);
        ull acc0 = lbp[0], acc1 = lbp[1];
#pragma unroll 8
        for (int d = 0; d < ADIM; d++) {
            ull s = dup2(a_s[pt][d]);
            const ull* wp = (const ull*)(Ws + d * KDIM + c4);
            acc0 = ffma2(s, wp[0], acc0);
            acc1 = ffma2(s, wp[1], acc1);
        }
        float2 u0 = unpack2(acc0), u1 = unpack2(acc1);
        float4 o; o.x = u0.x; o.y = u0.y; o.z = u1.x; o.w = u1.y;
        *(float4*)(g_cloud + (p0 + pt) * KDIM + c4) = o;
    }
}

// ---------------- kernel 5: projection GEMM (f32x2, transposed cloud) ----------
// block: 64 points x 128 cols; 256 threads; thread: 4 point-pairs x 4 cols.
// cloud tile stored transposed so point-pairs load as 8B LDS (broadcast).
#define CT_STRIDE 66
__global__ __launch_bounds__(256) void proj_kernel(
    const float* __restrict__ proj_W, const float* __restrict__ proj_b,
    float* __restrict__ tokens)
{
    __shared__ float csT[KDIM][CT_STRIDE]; // transposed: [k][pt], 16.5KB
    const int tid = threadIdx.x;
    const int p0 = blockIdx.x * 64;
    const int col0 = blockIdx.y * 128;

    // transpose-fill from g_cloud[(p0+pt)][k]
    for (int i = tid; i < 64 * 16; i += 256) {
        int pt = i >> 4, k4 = (i & 15) * 4;
        float4 v = *(const float4*)(g_cloud + (long)(p0 + pt) * KDIM + k4);
        csT[k4 + 0][pt] = v.x;
        csT[k4 + 1][pt] = v.y;
        csT[k4 + 2][pt] = v.z;
        csT[k4 + 3][pt] = v.w;
    }
    __syncthreads();

    const int cg = (tid & 31) * 4;     // col within 128-col block
    const int pg = (tid >> 5) * 8;     // point group of 8 (even → 8B aligned)

    ull acc[4][4]; // [point-pair][col]
#pragma unroll
    for (int i = 0; i < 4; i++)
#pragma unroll
        for (int j = 0; j < 4; j++) acc[i][j] = 0ULL;

#pragma unroll 4
    for (int k = 0; k < KDIM; k++) {
        const ull* sp = (const ull*)&csT[k][pg];  // broadcast within warp
        ull s0 = sp[0], s1 = sp[1], s2 = sp[2], s3 = sp[3];
        float4 w4 = *(const float4*)(proj_W + (long)k * DMODEL + col0 + cg);
        ull w0 = dup2(w4.x), w1 = dup2(w4.y), w2 = dup2(w4.z), w3 = dup2(w4.w);
        acc[0][0]=ffma2(s0,w0,acc[0][0]); acc[0][1]=ffma2(s0,w1,acc[0][1]); acc[0][2]=ffma2(s0,w2,acc[0][2]); acc[0][3]=ffma2(s0,w3,acc[0][3]);
        acc[1][0]=ffma2(s1,w0,acc[1][0]); acc[1][1]=ffma2(s1,w1,acc[1][1]); acc[1][2]=ffma2(s1,w2,acc[1][2]); acc[1][3]=ffma2(s1,w3,acc[1][3]);
        acc[2][0]=ffma2(s2,w0,acc[2][0]); acc[2][1]=ffma2(s2,w1,acc[2][1]); acc[2][2]=ffma2(s2,w2,acc[2][2]); acc[2][3]=ffma2(s2,w3,acc[2][3]);
        acc[3][0]=ffma2(s3,w0,acc[3][0]); acc[3][1]=ffma2(s3,w1,acc[3][1]); acc[3][2]=ffma2(s3,w2,acc[3][2]); acc[3][3]=ffma2(s3,w3,acc[3][3]);
    }
    float4 pb = *(const float4*)(proj_b + col0 + cg);
#pragma unroll
    for (int i = 0; i < 4; i++) {
        float2 a0 = unpack2(acc[i][0]);
        float2 a1 = unpack2(acc[i][1]);
        float2 a2 = unpack2(acc[i][2]);
        float2 a3 = unpack2(acc[i][3]);
        float4 olo, ohi;
        olo.x = a0.x + pb.x; olo.y = a1.x + pb.y; olo.z = a2.x + pb.z; olo.w = a3.x + pb.w;
        ohi.x = a0.y + pb.x; ohi.y = a1.y + pb.y; ohi.z = a2.y + pb.z; ohi.w = a3.y + pb.w;
        *(float4*)(tokens + (long)(p0 + pg + 2*i    ) * DMODEL + col0 + cg) = olo;
        *(float4*)(tokens + (long)(p0 + pg + 2*i + 1) * DMODEL + col0 + cg) = ohi;
    }
}

// ---------------- launcher ----------------
extern "C" void kernel_launch(void* const* d_in, const int* in_sizes, int n_in,
                              void* d_out, int out_size)
{
    const float* x      = (const float*)d_in[0];
    const float* W1     = (const float*)d_in[1];
    const float* b1     = (const float*)d_in[2];
    const float* W2     = (const float*)d_in[3];
    const float* b2     = (const float*)d_in[4];
    const float* lift_W = (const float*)d_in[5];
    const float* lift_b = (const float*)d_in[6];
    const float* mu     = (const float*)d_in[7];
    const float* sigma  = (const float*)d_in[8];
    const float* proj_W = (const float*)d_in[9];
    const float* proj_b = (const float*)d_in[10];

    float* tokens = (float*)d_out;                        // [B,256,1024]
    float* ystar  = tokens + (long)BATCH * KSEL * DMODEL; // [B,4096]

    const int salSmem = (IDIM * HID + SAL_TILE_PTS * SX_STRIDE) * sizeof(float); // 98048 B
    cudaFuncSetAttribute(saliency_kernel, cudaFuncAttributeMaxDynamicSharedMemorySize, salSmem);

    saliency_kernel<<<BATCH * (NPTS / (SAL_TILE_PTS * SAL_TILES)), 256, salSmem>>>(x, W1, b1, W2, b2);
    scan_kernel<<<BATCH, 1024>>>(ystar);
    topk_kernel<<<BATCH, 1024>>>(ystar);
    lift_kernel<<<BATCH * KSEL / 16, 256>>>(x, lift_W, lift_b, mu, sigma);
    dim3 pgrid(BATCH * KSEL / 64, DMODEL / 128);
    proj_kernel<<<pgrid, 256>>>(proj_W, proj_b, tokens);
}

// round 10
// speedup vs baseline: 1.2158x; 1.0668x over previous
#include <cuda_runtime.h>
#include <math.h>

#define BATCH 32
#define NPTS 4096
#define IDIM 125
#define ADIM 128
#define KDIM 64
#define DMODEL 1024
#define HID 64
#define KSEL 256
#define EPSV 1e-6f
#define CHUNK 512
#define NCHUNK (NPTS / CHUNK)          // 8
#define NCAND (NCHUNK * KSEL)          // 2048

typedef unsigned long long ull;

// ---------------- f32x2 packed-FMA helpers (sm_103a) ----------------
__device__ __forceinline__ ull pack2(float lo, float hi) {
    ull r; asm("mov.b64 %0, {%1, %2};" : "=l"(r) : "f"(lo), "f"(hi)); return r;
}
__device__ __forceinline__ ull dup2(float v) { return pack2(v, v); }
__device__ __forceinline__ float2 unpack2(ull v) {
    float2 f; asm("mov.b64 {%0, %1}, %2;" : "=f"(f.x), "=f"(f.y) : "l"(v)); return f;
}
__device__ __forceinline__ ull ffma2(ull a, ull b, ull c) {
    ull d; asm("fma.rn.f32x2 %0, %1, %2, %3;" : "=l"(d) : "l"(a), "l"(b), "l"(c)); return d;
}

// ---------------- scratch (device globals; no allocation allowed) ----------------
__device__ float g_sal[BATCH * NPTS];
__device__ float g_csal[BATCH * NPTS];
__device__ int   g_topidx[BATCH * KSEL];
__device__ float g_cloud[BATCH * KSEL * KDIM];   // [8192][64]
__device__ ull   g_part[BATCH * NCAND];          // stage-A survivors

// ---------------- kernel 1: fused saliency MLP (f32x2 packed) ----------------
#define SAL_TILE_PTS 128
#define SAL_TILES 2
#define SX_STRIDE 129
__global__ __launch_bounds__(256) void saliency_kernel(
    const float* __restrict__ x, const float* __restrict__ W1,
    const float* __restrict__ b1, const float* __restrict__ W2,
    const float* __restrict__ b2)
{
    extern __shared__ float dynsm[];
    float* W1s = dynsm;                 // [125][64]
    float* sx  = dynsm + IDIM * HID;    // [128][129]

    const int ptsPerBlock = SAL_TILE_PTS * SAL_TILES;       // 256
    const int groupsPerBatch = NPTS / ptsPerBlock;          // 16
    const int b  = blockIdx.x / groupsPerBatch;
    const int gp = blockIdx.x % groupsPerBatch;
    const int tid = threadIdx.x;

    for (int i = tid; i < IDIM * HID; i += 256) W1s[i] = W1[i];

    const int hg = tid & 7;        // 8 hidden groups of 8
    const int pg = tid >> 3;       // 32 point groups of 4
    const int h0 = hg * 8;

    const ull* b1p = (const ull*)(b1 + h0);
    ull bini[4] = {b1p[0], b1p[1], b1p[2], b1p[3]};
    float4 w2a = *(const float4*)(W2 + h0);
    float4 w2b = *(const float4*)(W2 + h0 + 4);
    const float w2s[8] = {w2a.x, w2a.y, w2a.z, w2a.w, w2b.x, w2b.y, w2b.z, w2b.w};
    const float bias = b2[0];

    for (int t = 0; t < SAL_TILES; t++) {
        const int p0 = (gp * SAL_TILES + t) * SAL_TILE_PTS;
        const float* xbase = x + ((long)b * NPTS + p0) * IDIM;
        __syncthreads();
        for (int i = tid; i < SAL_TILE_PTS * IDIM; i += 256) {
            int p = i / IDIM, d = i - p * IDIM;
            sx[p * SX_STRIDE + d] = xbase[i];
        }
        __syncthreads();

        ull A0[4], A1[4], A2[4], A3[4];
#pragma unroll
        for (int j = 0; j < 4; j++) { A0[j]=bini[j]; A1[j]=bini[j]; A2[j]=bini[j]; A3[j]=bini[j]; }

        const float* r0 = sx + (pg * 4 + 0) * SX_STRIDE;
        const float* r1 = sx + (pg * 4 + 1) * SX_STRIDE;
        const float* r2 = sx + (pg * 4 + 2) * SX_STRIDE;
        const float* r3 = sx + (pg * 4 + 3) * SX_STRIDE;
#pragma unroll 5
        for (int d = 0; d < IDIM; d++) {
            ull X0 = dup2(r0[d]);
            ull X1 = dup2(r1[d]);
            ull X2 = dup2(r2[d]);
            ull X3 = dup2(r3[d]);
            const ull* wrow = (const ull*)(W1s + d * HID + h0);
            ull w0 = wrow[0], w1 = wrow[1], w2 = wrow[2], w3 = wrow[3];
            A0[0]=ffma2(X0,w0,A0[0]); A0[1]=ffma2(X0,w1,A0[1]); A0[2]=ffma2(X0,w2,A0[2]); A0[3]=ffma2(X0,w3,A0[3]);
            A1[0]=ffma2(X1,w0,A1[0]); A1[1]=ffma2(X1,w1,A1[1]); A1[2]=ffma2(X1,w2,A1[2]); A1[3]=ffma2(X1,w3,A1[3]);
            A2[0]=ffma2(X2,w0,A2[0]); A2[1]=ffma2(X2,w1,A2[1]); A2[2]=ffma2(X2,w2,A2[2]); A2[3]=ffma2(X2,w3,A2[3]);
            A3[0]=ffma2(X3,w0,A3[0]); A3[1]=ffma2(X3,w1,A3[1]); A3[2]=ffma2(X3,w2,A3[2]); A3[3]=ffma2(X3,w3,A3[3]);
        }
        float s0 = 0.f, s1 = 0.f, s2 = 0.f, s3 = 0.f;
#pragma unroll
        for (int j = 0; j < 4; j++) {
            float2 u0 = unpack2(A0[j]), u1 = unpack2(A1[j]);
            float2 u2 = unpack2(A2[j]), u3 = unpack2(A3[j]);
            s0 = fmaf(fmaxf(u0.x,0.f), w2s[2*j], fmaf(fmaxf(u0.y,0.f), w2s[2*j+1], s0));
            s1 = fmaf(fmaxf(u1.x,0.f), w2s[2*j], fmaf(fmaxf(u1.y,0.f), w2s[2*j+1], s1));
            s2 = fmaf(fmaxf(u2.x,0.f), w2s[2*j], fmaf(fmaxf(u2.y,0.f), w2s[2*j+1], s2));
            s3 = fmaf(fmaxf(u3.x,0.f), w2s[2*j], fmaf(fmaxf(u3.y,0.f), w2s[2*j+1], s3));
        }
#pragma unroll
        for (int off = 4; off > 0; off >>= 1) {
            s0 += __shfl_down_sync(0xFFFFFFFFu, s0, off, 8);
            s1 += __shfl_down_sync(0xFFFFFFFFu, s1, off, 8);
            s2 += __shfl_down_sync(0xFFFFFFFFu, s2, off, 8);
            s3 += __shfl_down_sync(0xFFFFFFFFu, s3, off, 8);
        }
        if (hg == 0) {
            float* o = g_sal + b * NPTS + p0 + pg * 4;
            float4 r;
            r.x = 1.f / (1.f + expf(-(s0 + bias)));
            r.y = 1.f / (1.f + expf(-(s1 + bias)));
            r.z = 1.f / (1.f + expf(-(s2 + bias)));
            r.w = 1.f / (1.f + expf(-(s3 + bias)));
            *(float4*)o = r;
        }
    }
}

// ---------------- kernel 2: per-batch softmax + cumsum ----------------
__global__ __launch_bounds__(1024) void scan_kernel(float* __restrict__ ystar)
{
    __shared__ float wsum[32];
    __shared__ float woff[32];
    __shared__ float wesum[32];
    __shared__ float total_sh;

    const int b = blockIdx.x;
    const int tid = threadIdx.x;
    const int lane = tid & 31, wid = tid >> 5;

    float4 s4 = *(const float4*)(g_sal + b * NPTS + tid * 4);
    float s0 = s4.x;
    float s1 = s0 + s4.y;
    float s2 = s1 + s4.z;
    float s3 = s2 + s4.w;

    float e0 = expf(2.f * s4.x), e1 = expf(2.f * s4.y);
    float e2 = expf(2.f * s4.z), e3 = expf(2.f * s4.w);
    float esum = e0 + e1 + e2 + e3;

    float t = s3, incl = t;
#pragma unroll
    for (int off = 1; off < 32; off <<= 1) {
        float v = __shfl_up_sync(0xFFFFFFFFu, incl, off);
        if (lane >= off) incl += v;
    }
    float er = esum;
#pragma unroll
    for (int off = 16; off > 0; off >>= 1) er += __shfl_down_sync(0xFFFFFFFFu, er, off);
    if (lane == 31) wsum[wid] = incl;
    if (lane == 0)  wesum[wid] = er;
    __syncthreads();
    if (wid == 0) {
        float v = wsum[lane];
        float inc = v;
#pragma unroll
        for (int off = 1; off < 32; off <<= 1) {
            float u = __shfl_up_sync(0xFFFFFFFFu, inc, off);
            if (lane >= off) inc += u;
        }
        woff[lane] = inc - v;
        float es = wesum[lane];
#pragma unroll
        for (int off = 16; off > 0; off >>= 1) es += __shfl_down_sync(0xFFFFFFFFu, es, off);
        if (lane == 0) total_sh = es;
    }
    __syncthreads();

    float base = woff[wid] + (incl - t);
    const float invn = 1.f / (float)NPTS;
    float4 c4;
    c4.x = (base + s0) * invn;
    c4.y = (base + s1) * invn;
    c4.z = (base + s2) * invn;
    c4.w = (base + s3) * invn;
    *(float4*)(g_csal + b * NPTS + tid * 4) = c4;

    float invtot = 1.f / total_sh;
    float4 y4;
    y4.x = e0 * invtot; y4.y = e1 * invtot; y4.z = e2 * invtot; y4.w = e3 * invtot;
    *(float4*)(ystar + b * NPTS + tid * 4) = y4;
}

// ---------------- top-k helpers ----------------
__device__ __forceinline__ ull make_key(float val, int idx) {
    unsigned u = __float_as_uint(val);
    unsigned m = (u & 0x80000000u) ? ~u : (u | 0x80000000u);
    unsigned inv = ~m;   // ascending key sort == descending value
    return ((ull)inv << 32) | (unsigned)idx;
}

// ---------------- kernel 3a: per-chunk top-256 (sorted) ----------------
// grid BATCH*NCHUNK = 256 blocks, 256 threads; sort CHUNK=512 keys ascending.
__global__ __launch_bounds__(256) void topk_a(const float* __restrict__ ystar)
{
    __shared__ ull keys[CHUNK];
    const int b = blockIdx.x >> 3;
    const int c = blockIdx.x & 7;
    const int tid = threadIdx.x;
    const int base = c * CHUNK;

    for (int i = tid; i < CHUNK; i += 256) {
        int gi = base + i;
        keys[i] = make_key(ystar[b * NPTS + gi], gi);
    }
    __syncthreads();

    for (int k = 2; k <= CHUNK; k <<= 1) {
        for (int j = k >> 1; j > 0; j >>= 1) {
#pragma unroll 2
            for (int i = tid; i < CHUNK; i += 256) {
                int ixj = i ^ j;
                if (ixj > i) {
                    bool up = ((i & k) == 0);
                    ull a = keys[i], d = keys[ixj];
                    if ((a > d) == up) { keys[i] = d; keys[ixj] = a; }
                }
            }
            __syncthreads();
        }
    }
    // keys[0..255] = top 256 of this chunk (sorted)
    g_part[b * NCAND + c * KSEL + tid] = keys[tid];
}

// ---------------- kernel 3b: per-batch final top-256 from 2048 candidates ----
// grid BATCH blocks, 1024 threads; full bitonic sort of 2048 keys.
__global__ __launch_bounds__(1024) void topk_b()
{
    __shared__ ull keys[NCAND];
    const int b = blockIdx.x;
    const int tid = threadIdx.x;

    keys[tid]        = g_part[b * NCAND + tid];
    keys[tid + 1024] = g_part[b * NCAND + tid + 1024];
    __syncthreads();

    for (int k = 2; k <= NCAND; k <<= 1) {
        for (int j = k >> 1; j > 0; j >>= 1) {
#pragma unroll 2
            for (int i = tid; i < NCAND; i += 1024) {
                int ixj = i ^ j;
                if (ixj > i) {
                    bool up = ((i & k) == 0);
                    ull a = keys[i], d = keys[ixj];
                    if ((a > d) == up) { keys[i] = d; keys[ixj] = a; }
                }
            }
            __syncthreads();
        }
    }
    if (tid < KSEL)
        g_topidx[b * KSEL + tid] = (int)(keys[tid] & 0xFFFFFFFFu);
}

// ---------------- kernel 4: anchor + normalize + lift ----------------
#define AS_STRIDE 132
__global__ __launch_bounds__(256) void lift_kernel(
    const float* __restrict__ x, const float* __restrict__ lift_W,
    const float* __restrict__ lift_b, const float* __restrict__ mu,
    const float* __restrict__ sigma)
{
    __shared__ float Ws[ADIM * KDIM];      // 32KB
    __shared__ float a_s[16][AS_STRIDE];   // 8.25KB

    const int tid = threadIdx.x;
    const int p0 = blockIdx.x * 16;

    for (int i = tid; i < ADIM * KDIM; i += 256) Ws[i] = lift_W[i];

    {
        const int grp = tid >> 4;
        const int sub = tid & 15;
        const int gk = p0 + grp;
        const int b = gk / KSEL;
        const int idx = g_topidx[gk];
        const float* xr = x + ((long)b * NPTS + idx) * IDIM;
        float sal = g_sal[b * NPTS + idx];
        float csv = g_csal[b * NPTS + idx];
        float pos = (float)idx * (1.f / (float)(NPTS - 1));

        float v[8];
#pragma unroll
        for (int q = 0; q < 8; q++) {
            int d = sub * 8 + q;
            float val;
            if (d < IDIM)       val = xr[d];
            else if (d == 125)  val = sal;
            else if (d == 126)  val = pos;
            else                val = csv;
            v[q] = val;
        }
        float ss = 0.f;
#pragma unroll
        for (int q = 0; q < 8; q++) ss = fmaf(v[q], v[q], ss);
#pragma unroll
        for (int off = 8; off > 0; off >>= 1)
            ss += __shfl_xor_sync(0xFFFFFFFFu, ss, off, 16);
        float inv_nrm = 1.f / (sqrtf(ss) + EPSV);
#pragma unroll
        for (int q = 0; q < 8; q++) {
            int d = sub * 8 + q;
            a_s[grp][d] = (v[q] * inv_nrm - mu[d]) / sigma[d];
        }
    }
    __syncthreads();

    {
        const int pt = tid >> 4;
        const int c4 = (tid & 15) * 4;
        const ull* lbp = (const ull*)(lift_b + c4);
        ull acc0 = lbp[0], acc1 = lbp[1];
#pragma unroll 8
        for (int d = 0; d < ADIM; d++) {
            ull s = dup2(a_s[pt][d]);
            const ull* wp = (const ull*)(Ws + d * KDIM + c4);
            acc0 = ffma2(s, wp[0], acc0);
            acc1 = ffma2(s, wp[1], acc1);
        }
        float2 u0 = unpack2(acc0), u1 = unpack2(acc1);
        float4 o; o.x = u0.x; o.y = u0.y; o.z = u1.x; o.w = u1.y;
        *(float4*)(g_cloud + (p0 + pt) * KDIM + c4) = o;
    }
}

// ---------------- kernel 5: projection GEMM (f32x2, transposed cloud) ----------
#define CT_STRIDE 66
__global__ __launch_bounds__(256) void proj_kernel(
    const float* __restrict__ proj_W, const float* __restrict__ proj_b,
    float* __restrict__ tokens)
{
    __shared__ float csT[KDIM][CT_STRIDE]; // transposed: [k][pt]
    const int tid = threadIdx.x;
    const int p0 = blockIdx.x * 64;
    const int col0 = blockIdx.y * 128;

    for (int i = tid; i < 64 * 16; i += 256) {
        int pt = i >> 4, k4 = (i & 15) * 4;
        float4 v = *(const float4*)(g_cloud + (long)(p0 + pt) * KDIM + k4);
        csT[k4 + 0][pt] = v.x;
        csT[k4 + 1][pt] = v.y;
        csT[k4 + 2][pt] = v.z;
        csT[k4 + 3][pt] = v.w;
    }
    __syncthreads();

    const int cg = (tid & 31) * 4;
    const int pg = (tid >> 5) * 8;

    ull acc[4][4];
#pragma unroll
    for (int i = 0; i < 4; i++)
#pragma unroll
        for (int j = 0; j < 4; j++) acc[i][j] = 0ULL;

#pragma unroll 4
    for (int k = 0; k < KDIM; k++) {
        const ull* sp = (const ull*)&csT[k][pg];
        ull s0 = sp[0], s1 = sp[1], s2 = sp[2], s3 = sp[3];
        float4 w4 = *(const float4*)(proj_W + (long)k * DMODEL + col0 + cg);
        ull w0 = dup2(w4.x), w1 = dup2(w4.y), w2 = dup2(w4.z), w3 = dup2(w4.w);
        acc[0][0]=ffma2(s0,w0,acc[0][0]); acc[0][1]=ffma2(s0,w1,acc[0][1]); acc[0][2]=ffma2(s0,w2,acc[0][2]); acc[0][3]=ffma2(s0,w3,acc[0][3]);
        acc[1][0]=ffma2(s1,w0,acc[1][0]); acc[1][1]=ffma2(s1,w1,acc[1][1]); acc[1][2]=ffma2(s1,w2,acc[1][2]); acc[1][3]=ffma2(s1,w3,acc[1][3]);
        acc[2][0]=ffma2(s2,w0,acc[2][0]); acc[2][1]=ffma2(s2,w1,acc[2][1]); acc[2][2]=ffma2(s2,w2,acc[2][2]); acc[2][3]=ffma2(s2,w3,acc[2][3]);
        acc[3][0]=ffma2(s3,w0,acc[3][0]); acc[3][1]=ffma2(s3,w1,acc[3][1]); acc[3][2]=ffma2(s3,w2,acc[3][2]); acc[3][3]=ffma2(s3,w3,acc[3][3]);
    }
    float4 pb = *(const float4*)(proj_b + col0 + cg);
#pragma unroll
    for (int i = 0; i < 4; i++) {
        float2 a0 = unpack2(acc[i][0]);
        float2 a1 = unpack2(acc[i][1]);
        float2 a2 = unpack2(acc[i][2]);
        float2 a3 = unpack2(acc[i][3]);
        float4 olo, ohi;
        olo.x = a0.x + pb.x; olo.y = a1.x + pb.y; olo.z = a2.x + pb.z; olo.w = a3.x + pb.w;
        ohi.x = a0.y + pb.x; ohi.y = a1.y + pb.y; ohi.z = a2.y + pb.z; ohi.w = a3.y + pb.w;
        *(float4*)(tokens + (long)(p0 + pg + 2*i    ) * DMODEL + col0 + cg) = olo;
        *(float4*)(tokens + (long)(p0 + pg + 2*i + 1) * DMODEL + col0 + cg) = ohi;
    }
}

// ---------------- launcher ----------------
extern "C" void kernel_launch(void* const* d_in, const int* in_sizes, int n_in,
                              void* d_out, int out_size)
{
    const float* x      = (const float*)d_in[0];
    const float* W1     = (const float*)d_in[1];
    const float* b1     = (const float*)d_in[2];
    const float* W2     = (const float*)d_in[3];
    const float* b2     = (const float*)d_in[4];
    const float* lift_W = (const float*)d_in[5];
    const float* lift_b = (const float*)d_in[6];
    const float* mu     = (const float*)d_in[7];
    const float* sigma  = (const float*)d_in[8];
    const float* proj_W = (const float*)d_in[9];
    const float* proj_b = (const float*)d_in[10];

    float* tokens = (float*)d_out;                        // [B,256,1024]
    float* ystar  = tokens + (long)BATCH * KSEL * DMODEL; // [B,4096]

    const int salSmem = (IDIM * HID + SAL_TILE_PTS * SX_STRIDE) * sizeof(float); // 98048 B
    cudaFuncSetAttribute(saliency_kernel, cudaFuncAttributeMaxDynamicSharedMemorySize, salSmem);

    saliency_kernel<<<BATCH * (NPTS / (SAL_TILE_PTS * SAL_TILES)), 256, salSmem>>>(x, W1, b1, W2, b2);
    scan_kernel<<<BATCH, 1024>>>(ystar);
    topk_a<<<BATCH * NCHUNK, 256>>>(ystar);
    topk_b<<<BATCH, 1024>>>();
    lift_kernel<<<BATCH * KSEL / 16, 256>>>(x, lift_W, lift_b, mu, sigma);
    dim3 pgrid(BATCH * KSEL / 64, DMODEL / 128);
    proj_kernel<<<pgrid, 256>>>(proj_W, proj_b, tokens);
}